// round 3
// baseline (speedup 1.0000x reference)
#include <cuda_runtime.h>
#include <math.h>

// Problem constants
constexpr int T_SEQ = 2048;   // sequence length
constexpr int CH    = 64;     // head dim (C3 = 3 * 64 = 192)
constexpr int BQ    = 64;     // query tile
constexpr int BK    = 64;     // key tile
constexpr int SST   = 68;     // smem row stride (pad: multiple of 4, odd/32 residue -> conflict-light)
constexpr int NTHREADS = 256;

// Dynamic smem layout (floats):
//   Qs [CH][SST]   row = c, col = tq   (scaled Q, loaded once)
//   Ks [CH][SST]   row = c, col = tk   (scaled K, per tile)
//   Vt [BK][SST]   row = tk, col = c   (V transposed, per tile)
//   Ps [BQ][SST]   scores -> probs; reused as O staging at the end
//   m_s[BQ], l_s[BQ], c_s[BQ]
constexpr int SMEM_FLOATS = 4 * 64 * SST + 3 * BQ;

__global__ __launch_bounds__(NTHREADS, 1)
void qkv_attn_kernel(const float* __restrict__ qkv, float* __restrict__ out)
{
    extern __shared__ float sm[];
    float* Qs  = sm;
    float* Ks  = Qs + CH * SST;
    float* Vt  = Ks + CH * SST;
    float* Ps  = Vt + BK * SST;
    float* m_s = Ps + BQ * SST;
    float* l_s = m_s + BQ;
    float* c_s = l_s + BQ;

    const int b   = blockIdx.y;
    const int q0  = blockIdx.x * BQ;
    const int tid = threadIdx.x;
    const int tx  = tid & 15;   // 16 col-groups (tk / c frags)
    const int ty  = tid >> 4;   // 16 row-groups (tq frags)

    const float scale = 0.35355339059327373f;  // 1/sqrt(sqrt(64)), applied to both q and k

    const float* qb = qkv + (size_t)b * 3 * CH * T_SEQ;
    const float* kb = qb + (size_t)CH * T_SEQ;
    const float* vb = qb + (size_t)2 * CH * T_SEQ;

    // ---- load Q tile (scaled), [c][tq] ----
#pragma unroll
    for (int r = 0; r < 4; r++) {
        int f   = tid + r * NTHREADS;       // 0..1023 float4 slots
        int row = f >> 4;                   // c
        int c4  = (f & 15) << 2;            // tq base
        float4 v = *(const float4*)(qb + (size_t)row * T_SEQ + q0 + c4);
        v.x *= scale; v.y *= scale; v.z *= scale; v.w *= scale;
        *(float4*)(Qs + row * SST + c4) = v;
    }
    if (tid < BQ) {
        m_s[tid] = __int_as_float(0xff800000); // -inf
        l_s[tid] = 0.0f;
    }

    float o[4][4];
#pragma unroll
    for (int i = 0; i < 4; i++)
#pragma unroll
        for (int j = 0; j < 4; j++) o[i][j] = 0.0f;

    for (int kt = 0; kt < T_SEQ / BK; kt++) {
        const int s0 = kt * BK;
        __syncthreads();   // previous tile's PV reads of Ks/Vt/Ps are done

        // ---- load K tile (scaled) [c][tk], and V transposed [tk][c] ----
#pragma unroll
        for (int r = 0; r < 4; r++) {
            int f   = tid + r * NTHREADS;
            int row = f >> 4;               // c
            int c4  = (f & 15) << 2;        // tk base
            float4 kv = *(const float4*)(kb + (size_t)row * T_SEQ + s0 + c4);
            kv.x *= scale; kv.y *= scale; kv.z *= scale; kv.w *= scale;
            *(float4*)(Ks + row * SST + c4) = kv;
            float4 vv = *(const float4*)(vb + (size_t)row * T_SEQ + s0 + c4);
            Vt[(c4 + 0) * SST + row] = vv.x;
            Vt[(c4 + 1) * SST + row] = vv.y;
            Vt[(c4 + 2) * SST + row] = vv.z;
            Vt[(c4 + 3) * SST + row] = vv.w;
        }
        __syncthreads();

        // ---- S = (Q*s)^T (K*s) : acc[tq][tk], 4x4 per thread ----
        float acc[4][4];
#pragma unroll
        for (int i = 0; i < 4; i++)
#pragma unroll
            for (int j = 0; j < 4; j++) acc[i][j] = 0.0f;

#pragma unroll 8
        for (int c = 0; c < CH; c++) {
            float4 qf = *(const float4*)(Qs + c * SST + ty * 4);
            float4 kf = *(const float4*)(Ks + c * SST + tx * 4);
            acc[0][0] += qf.x * kf.x; acc[0][1] += qf.x * kf.y; acc[0][2] += qf.x * kf.z; acc[0][3] += qf.x * kf.w;
            acc[1][0] += qf.y * kf.x; acc[1][1] += qf.y * kf.y; acc[1][2] += qf.y * kf.z; acc[1][3] += qf.y * kf.w;
            acc[2][0] += qf.z * kf.x; acc[2][1] += qf.z * kf.y; acc[2][2] += qf.z * kf.z; acc[2][3] += qf.z * kf.w;
            acc[3][0] += qf.w * kf.x; acc[3][1] += qf.w * kf.y; acc[3][2] += qf.w * kf.z; acc[3][3] += qf.w * kf.w;
        }
#pragma unroll
        for (int i = 0; i < 4; i++) {
            *(float4*)(Ps + (ty * 4 + i) * SST + tx * 4) =
                make_float4(acc[i][0], acc[i][1], acc[i][2], acc[i][3]);
        }
        __syncthreads();

        // ---- online softmax: 4 threads per row, 16 cols each ----
        {
            const int row = tid >> 2;
            const int seg = (tid & 3) << 4;
            float* pr = Ps + row * SST + seg;

            float mx = __int_as_float(0xff800000);
#pragma unroll
            for (int j = 0; j < 16; j++) mx = fmaxf(mx, pr[j]);
            mx = fmaxf(mx, __shfl_xor_sync(0xffffffffu, mx, 1));
            mx = fmaxf(mx, __shfl_xor_sync(0xffffffffu, mx, 2));

            float m_old = m_s[row];
            float m_new = fmaxf(m_old, mx);

            float sum = 0.0f;
#pragma unroll
            for (int j = 0; j < 16; j++) {
                float p = __expf(pr[j] - m_new);
                pr[j] = p;
                sum += p;
            }
            sum += __shfl_xor_sync(0xffffffffu, sum, 1);
            sum += __shfl_xor_sync(0xffffffffu, sum, 2);

            if ((tid & 3) == 0) {
                float cf = __expf(m_old - m_new);   // 0 on first tile (-inf)
                l_s[row] = l_s[row] * cf + sum;
                m_s[row] = m_new;
                c_s[row] = cf;
            }
        }
        __syncthreads();

        // ---- rescale O, then O += P @ V^T  (o[tq][c]) ----
#pragma unroll
        for (int i = 0; i < 4; i++) {
            float cf = c_s[ty * 4 + i];
#pragma unroll
            for (int j = 0; j < 4; j++) o[i][j] *= cf;
        }

#pragma unroll 4
        for (int tk = 0; tk < BK; tk += 4) {
            float pfa[4][4];
#pragma unroll
            for (int i = 0; i < 4; i++) {
                float4 t = *(const float4*)(Ps + (ty * 4 + i) * SST + tk);
                pfa[i][0] = t.x; pfa[i][1] = t.y; pfa[i][2] = t.z; pfa[i][3] = t.w;
            }
#pragma unroll
            for (int kk = 0; kk < 4; kk++) {
                float4 vf = *(const float4*)(Vt + (tk + kk) * SST + tx * 4);
#pragma unroll
                for (int i = 0; i < 4; i++) {
                    o[i][0] += pfa[i][kk] * vf.x;
                    o[i][1] += pfa[i][kk] * vf.y;
                    o[i][2] += pfa[i][kk] * vf.z;
                    o[i][3] += pfa[i][kk] * vf.w;
                }
            }
        }
    }

    __syncthreads();
    // ---- epilogue: normalize, transpose through smem (reuse Ps as Osm[c][tq]), coalesced store ----
    {
        float linv[4];
#pragma unroll
        for (int i = 0; i < 4; i++) linv[i] = 1.0f / l_s[ty * 4 + i];
#pragma unroll
        for (int i = 0; i < 4; i++)
#pragma unroll
            for (int j = 0; j < 4; j++)
                Ps[(tx * 4 + j) * SST + ty * 4 + i] = o[i][j] * linv[i];
    }
    __syncthreads();

    float* ob = out + (size_t)b * CH * T_SEQ + q0;
#pragma unroll
    for (int r = 0; r < 4; r++) {
        int f   = tid + r * NTHREADS;
        int row = f >> 4;                  // c
        int c4  = (f & 15) << 2;           // tq base
        *(float4*)(ob + (size_t)row * T_SEQ + c4) =
            *(const float4*)(Ps + row * SST + c4);
    }
}

extern "C" void kernel_launch(void* const* d_in, const int* in_sizes, int n_in,
                              void* d_out, int out_size)
{
    (void)n_in; (void)out_size;
    const float* qkv = (const float*)d_in[0];
    float* out = (float*)d_out;

    const int n_batch = in_sizes[0] / (3 * CH * T_SEQ);   // 32

    constexpr size_t SMEM_BYTES = (size_t)SMEM_FLOATS * sizeof(float);  // ~70 KB
    cudaFuncSetAttribute(qkv_attn_kernel,
                         cudaFuncAttributeMaxDynamicSharedMemorySize,
                         (int)SMEM_BYTES);

    dim3 grid(T_SEQ / BQ, n_batch);
    qkv_attn_kernel<<<grid, NTHREADS, SMEM_BYTES>>>(qkv, out);
}

// round 4
// speedup vs baseline: 1.1022x; 1.1022x over previous
#include <cuda_runtime.h>
#include <math.h>

// Problem constants
constexpr int T_SEQ = 2048;
constexpr int CH    = 64;     // head dim
constexpr int BQ    = 128;    // query tile
constexpr int BK    = 128;    // key tile
constexpr int NTHREADS = 256;

// Smem layout (floats):
//   Qs [64][128]  row=c, col=tq   (scaled Q, loaded once)     8192
//   Ks [64][128]  row=c, col=tk   (scaled K, per tile)        8192
//   Vs [64][128]  row=c, col=tk   (V as-is, per tile)         8192
//   Ps [128][132] swizzled probs buffer                      16896
//   m_s/l_s/c_s [128] each                                     384
constexpr int PST = 132;
constexpr int SMEM_FLOATS = 3 * 64 * 128 + BQ * PST + 3 * BQ;  // 41856 -> ~163.5 KB

// Swizzled address into Ps: element (row, col) with col = cc*4 + e.
// Physical float offset = row*132 + ((cc ^ ((row>>2)&7))<<2) + e
__device__ __forceinline__ int ps_off(int row, int cc) {
    return row * PST + (((cc) ^ ((row >> 2) & 7)) << 2);
}

__global__ __launch_bounds__(NTHREADS, 1)
void qkv_attn_kernel(const float* __restrict__ qkv, float* __restrict__ out)
{
    extern __shared__ float sm[];
    float* Qs  = sm;
    float* Ks  = Qs + 64 * 128;
    float* Vs  = Ks + 64 * 128;
    float* Ps  = Vs + 64 * 128;
    float* m_s = Ps + BQ * PST;
    float* l_s = m_s + BQ;
    float* c_s = l_s + BQ;

    const int b   = blockIdx.y;
    const int q0  = blockIdx.x * BQ;
    const int tid = threadIdx.x;
    const int tx  = tid & 15;
    const int ty  = tid >> 4;

    const float scale = 0.35355339059327373f;  // 1/sqrt(sqrt(64))

    const float* qb = qkv + (size_t)b * 3 * CH * T_SEQ;
    const float* kb = qb + (size_t)CH * T_SEQ;
    const float* vb = qb + (size_t)2 * CH * T_SEQ;

    // ---- load Q tile (scaled), Qs[c][tq], 8 float4 per thread ----
#pragma unroll
    for (int r = 0; r < 8; r++) {
        int f   = tid + r * NTHREADS;       // 0..2047 float4 slots
        int row = f >> 5;                   // c (0..63)
        int c4  = (f & 31) << 2;            // tq base (0..124)
        float4 v = *(const float4*)(qb + (size_t)row * T_SEQ + q0 + c4);
        v.x *= scale; v.y *= scale; v.z *= scale; v.w *= scale;
        *(float4*)(Qs + row * 128 + c4) = v;
    }
    if (tid < BQ) {
        m_s[tid] = __int_as_float(0xff800000);  // -inf
        l_s[tid] = 0.0f;
    }

    // O accumulator: o[i][j] -> row c = ty*4+i ; col tq = tx*4+j (j<4) or 64+tx*4+(j-4)
    float o[4][8];
#pragma unroll
    for (int i = 0; i < 4; i++)
#pragma unroll
        for (int j = 0; j < 8; j++) o[i][j] = 0.0f;

    for (int kt = 0; kt < T_SEQ / BK; kt++) {
        const int s0 = kt * BK;
        __syncthreads();  // prev PV reads of Ks/Vs/Ps complete

        // ---- load K (scaled) and V tiles: [c][tk] ----
#pragma unroll
        for (int r = 0; r < 8; r++) {
            int f   = tid + r * NTHREADS;
            int row = f >> 5;
            int c4  = (f & 31) << 2;
            float4 kv = *(const float4*)(kb + (size_t)row * T_SEQ + s0 + c4);
            kv.x *= scale; kv.y *= scale; kv.z *= scale; kv.w *= scale;
            *(float4*)(Ks + row * 128 + c4) = kv;
            float4 vv = *(const float4*)(vb + (size_t)row * T_SEQ + s0 + c4);
            *(float4*)(Vs + row * 128 + c4) = vv;
        }
        __syncthreads();

        // ---- S = Q^T K : acc[r][cidx], 8x8 per thread ----
        // rows tq: {ty*4+r (r<4), 64+ty*4+(r-4)} ; cols tk: {tx*4+j, 64+tx*4+(j-4)}
        float acc[8][8];
#pragma unroll
        for (int i = 0; i < 8; i++)
#pragma unroll
            for (int j = 0; j < 8; j++) acc[i][j] = 0.0f;

#pragma unroll 4
        for (int c = 0; c < CH; c++) {
            float4 qa = *(const float4*)(Qs + c * 128 + ty * 4);
            float4 qb4 = *(const float4*)(Qs + c * 128 + 64 + ty * 4);
            float4 ka = *(const float4*)(Ks + c * 128 + tx * 4);
            float4 kb4 = *(const float4*)(Ks + c * 128 + 64 + tx * 4);
            float qr[8] = {qa.x, qa.y, qa.z, qa.w, qb4.x, qb4.y, qb4.z, qb4.w};
            float kr[8] = {ka.x, ka.y, ka.z, ka.w, kb4.x, kb4.y, kb4.z, kb4.w};
#pragma unroll
            for (int i = 0; i < 8; i++)
#pragma unroll
                for (int j = 0; j < 8; j++)
                    acc[i][j] += qr[i] * kr[j];
        }

        // ---- store S to swizzled Ps ----
#pragma unroll
        for (int r = 0; r < 8; r++) {
            int row = (r < 4) ? (ty * 4 + r) : (64 + ty * 4 + (r - 4));
            *(float4*)(Ps + ps_off(row, tx)) =
                make_float4(acc[r][0], acc[r][1], acc[r][2], acc[r][3]);
            *(float4*)(Ps + ps_off(row, 16 + tx)) =
                make_float4(acc[r][4], acc[r][5], acc[r][6], acc[r][7]);
        }
        __syncthreads();

        // ---- online softmax: 2 threads per row, interleaved even/odd chunks ----
        {
            const int row = tid >> 1;
            const int h   = tid & 1;

            float mx = __int_as_float(0xff800000);
            float4 pv[16];
#pragma unroll
            for (int i = 0; i < 16; i++) {
                int cc = 2 * i + h;
                pv[i] = *(const float4*)(Ps + ps_off(row, cc));
                mx = fmaxf(mx, fmaxf(fmaxf(pv[i].x, pv[i].y), fmaxf(pv[i].z, pv[i].w)));
            }
            mx = fmaxf(mx, __shfl_xor_sync(0xffffffffu, mx, 1));

            float m_old = m_s[row];
            float m_new = fmaxf(m_old, mx);

            float sum = 0.0f;
#pragma unroll
            for (int i = 0; i < 16; i++) {
                int cc = 2 * i + h;
                pv[i].x = __expf(pv[i].x - m_new);
                pv[i].y = __expf(pv[i].y - m_new);
                pv[i].z = __expf(pv[i].z - m_new);
                pv[i].w = __expf(pv[i].w - m_new);
                sum += pv[i].x + pv[i].y + pv[i].z + pv[i].w;
                *(float4*)(Ps + ps_off(row, cc)) = pv[i];
            }
            sum += __shfl_xor_sync(0xffffffffu, sum, 1);

            if (h == 0) {
                float cf = __expf(m_old - m_new);  // 0 on first tile
                l_s[row] = l_s[row] * cf + sum;
                m_s[row] = m_new;
                c_s[row] = cf;
            }
        }
        __syncthreads();

        // ---- rescale O by cf[tq], then O[c][tq] += V[c][tk] * P[tq][tk] ----
        {
            float cf[8];
#pragma unroll
            for (int j = 0; j < 8; j++) {
                int tq = (j < 4) ? (tx * 4 + j) : (64 + tx * 4 + (j - 4));
                cf[j] = c_s[tq];
            }
#pragma unroll
            for (int i = 0; i < 4; i++)
#pragma unroll
                for (int j = 0; j < 8; j++) o[i][j] *= cf[j];
        }

#pragma unroll 4
        for (int cc = 0; cc < 32; cc++) {   // tk chunks of 4
            float4 vf[4];
#pragma unroll
            for (int i = 0; i < 4; i++)
                vf[i] = *(const float4*)(Vs + (ty * 4 + i) * 128 + cc * 4);
            float4 pf[8];
#pragma unroll
            for (int j = 0; j < 8; j++) {
                int row = (j < 4) ? (tx * 4 + j) : (64 + tx * 4 + (j - 4));
                pf[j] = *(const float4*)(Ps + ps_off(row, cc));
            }
#pragma unroll
            for (int i = 0; i < 4; i++)
#pragma unroll
                for (int j = 0; j < 8; j++) {
                    o[i][j] += vf[i].x * pf[j].x;
                    o[i][j] += vf[i].y * pf[j].y;
                    o[i][j] += vf[i].z * pf[j].z;
                    o[i][j] += vf[i].w * pf[j].w;
                }
        }
    }

    // ---- epilogue: divide by l, store O[c][tq] directly (coalesced) ----
    {
        float linv[8];
#pragma unroll
        for (int j = 0; j < 8; j++) {
            int tq = (j < 4) ? (tx * 4 + j) : (64 + tx * 4 + (j - 4));
            linv[j] = 1.0f / l_s[tq];
        }
        float* ob = out + (size_t)b * CH * T_SEQ + q0;
#pragma unroll
        for (int i = 0; i < 4; i++) {
            int c = ty * 4 + i;
            *(float4*)(ob + (size_t)c * T_SEQ + tx * 4) =
                make_float4(o[i][0] * linv[0], o[i][1] * linv[1],
                            o[i][2] * linv[2], o[i][3] * linv[3]);
            *(float4*)(ob + (size_t)c * T_SEQ + 64 + tx * 4) =
                make_float4(o[i][4] * linv[4], o[i][5] * linv[5],
                            o[i][6] * linv[6], o[i][7] * linv[7]);
        }
    }
}

extern "C" void kernel_launch(void* const* d_in, const int* in_sizes, int n_in,
                              void* d_out, int out_size)
{
    (void)n_in; (void)out_size;
    const float* qkv = (const float*)d_in[0];
    float* out = (float*)d_out;

    const int n_batch = in_sizes[0] / (3 * CH * T_SEQ);   // 32

    constexpr size_t SMEM_BYTES = (size_t)SMEM_FLOATS * sizeof(float);  // ~163.5 KB
    cudaFuncSetAttribute(qkv_attn_kernel,
                         cudaFuncAttributeMaxDynamicSharedMemorySize,
                         (int)SMEM_BYTES);

    dim3 grid(T_SEQ / BQ, n_batch);
    qkv_attn_kernel<<<grid, NTHREADS, SMEM_BYTES>>>(qkv, out);
}